// round 1
// baseline (speedup 1.0000x reference)
#include <cuda_runtime.h>
#include <math.h>

#define BB 128
#define NN 128
#define FF 16

// ---------------------------------------------------------------------------
// Quantized / folded weights. All activation scales (1/256) are folded into
// the consuming layer so activations are carried as integer-valued floats.
// ---------------------------------------------------------------------------
struct QWeights {
    float bnA[16], bnB[16];       // bn = x*bnA + bnB
    float W1x256[32][32];         // [j][k] = 256*qb(fr_w1[j][k]), k<30
    float b1x256[32];             // 256*qb(fr_b1)
    float W2t[15][32];            // [k][j] = qb(fr_w2[j][k]), j<30
    float b2x256[16];             // 256*qb(fr_b2)
    float W3t[6][16];             // [c][j] = qb(fr_w3[j][c]), j<15
    float b3x256[8];
    float Wo1t[45][24];           // [k][j]: j<16 -> 256*qb(fo_w1[j][k]); j=16..21 -> qb (eff part already x256)
    float bo1x256[48];
    float Wo2t[22][48];           // [k][j] = qb(fo_w2[j][k]), j<45
    float bo2x256[24];
    float Wo3t[6][24];            // [c][j] = qb(fo_w3[j][c]), j<22
    float bo3x256[8];
    float Wc1t[48][8];            // [k][c] = qb(fc_w1[c][k]), c<6 (pooled already x256)
    float bc1x256[48];
    float Wc2t[5][48];            // [o][k] = qb(fc_w2[k][o]) / 256
    float bc2[8];
};

__device__ QWeights g_qw;
__device__ __align__(16) float g_bn[BB * NN * 16];
__device__ __align__(16) float g_Ar[BB * NN * 32];
__device__ __align__(16) float g_As[BB * NN * 32];
__device__ float g_pooled[BB * 8];

__device__ __forceinline__ float qb(float x) {
    float y = fminf(fmaxf(x, -1.0f), 127.0f / 128.0f);
    return rintf(y * 128.0f) * (1.0f / 128.0f);
}

// clamp-to-[0,255] + round-half-even: the x256-scaled qrelu
__device__ __forceinline__ float qrelu_i(float p) {
    return rintf(fminf(fmaxf(p, 0.0f), 255.0f));
}

// ---------------------------------------------------------------------------
// Kernel 0: quantize + fold all weights, zero pooled accumulator.
// ---------------------------------------------------------------------------
__global__ void prep_kernel(
    const float* __restrict__ gamma, const float* __restrict__ beta,
    const float* __restrict__ mean,  const float* __restrict__ var,
    const float* __restrict__ fr_w1, const float* __restrict__ fr_b1,
    const float* __restrict__ fr_w2, const float* __restrict__ fr_b2,
    const float* __restrict__ fr_w3, const float* __restrict__ fr_b3,
    const float* __restrict__ fo_w1, const float* __restrict__ fo_b1,
    const float* __restrict__ fo_w2, const float* __restrict__ fo_b2,
    const float* __restrict__ fo_w3, const float* __restrict__ fo_b3,
    const float* __restrict__ fc_w1, const float* __restrict__ fc_b1,
    const float* __restrict__ fc_w2, const float* __restrict__ fc_b2)
{
    const int t = threadIdx.x;
    const int NT = 256;
    float* qwf = reinterpret_cast<float*>(&g_qw);
    const int qn = (int)(sizeof(QWeights) / 4);
    for (int i = t; i < qn; i += NT) qwf[i] = 0.0f;
    for (int i = t; i < BB * 8; i += NT) g_pooled[i] = 0.0f;
    __syncthreads();

    if (t < 16) {
        float s = gamma[t] / sqrtf(var[t] + 1e-3f);
        g_qw.bnA[t] = s;
        g_qw.bnB[t] = beta[t] - mean[t] * s;
    }
    for (int i = t; i < 32 * 30; i += NT) { int j = i / 30, k = i % 30; g_qw.W1x256[j][k] = 256.0f * qb(fr_w1[i]); }
    for (int i = t; i < 30; i += NT) g_qw.b1x256[i] = 256.0f * qb(fr_b1[i]);
    for (int i = t; i < 30 * 15; i += NT) { int j = i / 15, k = i % 15; g_qw.W2t[k][j] = qb(fr_w2[i]); }
    for (int i = t; i < 15; i += NT) g_qw.b2x256[i] = 256.0f * qb(fr_b2[i]);
    for (int i = t; i < 15 * 6; i += NT) { int j = i / 6, c = i % 6; g_qw.W3t[c][j] = qb(fr_w3[i]); }
    for (int i = t; i < 6; i += NT) g_qw.b3x256[i] = 256.0f * qb(fr_b3[i]);
    for (int i = t; i < 22 * 45; i += NT) {
        int j = i / 45, k = i % 45;
        float q = qb(fo_w1[i]);
        g_qw.Wo1t[k][j] = (j < 16) ? 256.0f * q : q;
    }
    for (int i = t; i < 45; i += NT) g_qw.bo1x256[i] = 256.0f * qb(fo_b1[i]);
    for (int i = t; i < 45 * 22; i += NT) { int j = i / 22, k = i % 22; g_qw.Wo2t[k][j] = qb(fo_w2[i]); }
    for (int i = t; i < 22; i += NT) g_qw.bo2x256[i] = 256.0f * qb(fo_b2[i]);
    for (int i = t; i < 22 * 6; i += NT) { int j = i / 6, c = i % 6; g_qw.Wo3t[c][j] = qb(fo_w3[i]); }
    for (int i = t; i < 6; i += NT) g_qw.bo3x256[i] = 256.0f * qb(fo_b3[i]);
    for (int i = t; i < 6 * 48; i += NT) { int c = i / 48, k = i % 48; g_qw.Wc1t[k][c] = qb(fc_w1[i]); }
    for (int i = t; i < 48; i += NT) g_qw.bc1x256[i] = 256.0f * qb(fc_b1[i]);
    for (int i = t; i < 48 * 5; i += NT) { int k = i / 5, o = i % 5; g_qw.Wc2t[o][k] = qb(fc_w2[i]) * (1.0f / 256.0f); }
    for (int i = t; i < 5; i += NT) g_qw.bc2[i] = qb(fc_b2[i]);
}

// ---------------------------------------------------------------------------
// Kernel A: per node -> bn, Ar = 256*(bn@W1r)+256*b1, As = 256*(bn@W1s)
// ---------------------------------------------------------------------------
__global__ void __launch_bounds__(128) node_pre_kernel(const float* __restrict__ x)
{
    __shared__ __align__(16) float sW1[32 * 32];
    __shared__ float sb1[32];
    __shared__ float sA[16], sB[16];
    const int t = threadIdx.x, b = blockIdx.x;

    const float* w1g = reinterpret_cast<const float*>(g_qw.W1x256);
    for (int i = t; i < 1024; i += 128) sW1[i] = w1g[i];
    if (t < 32) sb1[t] = g_qw.b1x256[t];
    if (t < 16) { sA[t] = g_qw.bnA[t]; sB[t] = g_qw.bnB[t]; }
    __syncthreads();

    const int n = t;
    const float* xp = x + (size_t)(b * NN + n) * 16;
    float bn[16];
#pragma unroll
    for (int j = 0; j < 16; j++) bn[j] = xp[j] * sA[j] + sB[j];

    float ar[32], as_[32];
#pragma unroll
    for (int k = 0; k < 32; k++) { ar[k] = sb1[k]; as_[k] = 0.0f; }
#pragma unroll
    for (int j = 0; j < 16; j++) {
        float bj = bn[j];
#pragma unroll
        for (int k = 0; k < 32; k++) {
            ar[k]  += bj * sW1[j * 32 + k];
            as_[k] += bj * sW1[(16 + j) * 32 + k];
        }
    }
    float* bno = &g_bn[(size_t)(b * NN + n) * 16];
#pragma unroll
    for (int j = 0; j < 16; j++) bno[j] = bn[j];
    float* aro = &g_Ar[(size_t)(b * NN + n) * 32];
    float* aso = &g_As[(size_t)(b * NN + n) * 32];
#pragma unroll
    for (int k = 0; k < 32; k++) { aro[k] = ar[k]; aso[k] = as_[k]; }
}

// ---------------------------------------------------------------------------
// Kernel B: block (r, b) -> 127 edges (one per thread) + node MLP for node r.
// All arithmetic from h1 onward is exact integer math in fp32.
// ---------------------------------------------------------------------------
__global__ void __launch_bounds__(128) edge_kernel()
{
    __shared__ __align__(16) float sW2[15][32];
    __shared__ float sb2[16];
    __shared__ __align__(16) float sW3[6][16];
    __shared__ float sb3[8];
    __shared__ float sAr[32];
    __shared__ float sBn[16];
    __shared__ float sEff[6];
    __shared__ float sHo1[45];
    __shared__ float sHo2[22];

    const int t = threadIdx.x;
    const int r = blockIdx.x;
    const int b = blockIdx.y;

    {
        const float* w2g = reinterpret_cast<const float*>(g_qw.W2t);
        for (int i = t; i < 15 * 32; i += 128) (&sW2[0][0])[i] = w2g[i];
        const float* w3g = reinterpret_cast<const float*>(g_qw.W3t);
        if (t < 96) (&sW3[0][0])[t] = w3g[t];
        if (t < 15) sb2[t] = g_qw.b2x256[t];
        if (t < 6)  { sb3[t] = g_qw.b3x256[t]; sEff[t] = 0.0f; }
        if (t < 32) sAr[t] = g_Ar[(size_t)(b * NN + r) * 32 + t];
        if (t < 16) sBn[t] = g_bn[(size_t)(b * NN + r) * 16 + t];
    }
    __syncthreads();

    const int s = t;  // sender index; thread s==r contributes zero
    const float4* as4 = reinterpret_cast<const float4*>(&g_As[(size_t)(b * NN + s) * 32]);

    float h1[32];
#pragma unroll
    for (int i = 0; i < 8; i++) {
        float4 v = as4[i];
        h1[4 * i + 0] = v.x; h1[4 * i + 1] = v.y;
        h1[4 * i + 2] = v.z; h1[4 * i + 3] = v.w;
    }
#pragma unroll
    for (int k = 0; k < 30; k++) h1[k] = qrelu_i(sAr[k] + h1[k]);
    h1[30] = 0.0f; h1[31] = 0.0f;

    float h2[16];
#pragma unroll
    for (int k = 0; k < 15; k++) {
        float a = sb2[k];
        const float4* w = reinterpret_cast<const float4*>(&sW2[k][0]);
#pragma unroll
        for (int j = 0; j < 8; j++) {
            float4 wv = w[j];
            a += h1[4 * j + 0] * wv.x;
            a += h1[4 * j + 1] * wv.y;
            a += h1[4 * j + 2] * wv.z;
            a += h1[4 * j + 3] * wv.w;
        }
        h2[k] = qrelu_i(a);
    }
    h2[15] = 0.0f;

    float e[6];
#pragma unroll
    for (int c = 0; c < 6; c++) {
        float a = sb3[c];
        const float4* w = reinterpret_cast<const float4*>(&sW3[c][0]);
#pragma unroll
        for (int j = 0; j < 4; j++) {
            float4 wv = w[j];
            a += h2[4 * j + 0] * wv.x;
            a += h2[4 * j + 1] * wv.y;
            a += h2[4 * j + 2] * wv.z;
            a += h2[4 * j + 3] * wv.w;
        }
        e[c] = (s == r) ? 0.0f : qrelu_i(a);
    }

    // warp reduction (exact: integer-valued floats, sums < 2^24)
#pragma unroll
    for (int o = 16; o > 0; o >>= 1) {
#pragma unroll
        for (int c = 0; c < 6; c++) e[c] += __shfl_xor_sync(0xffffffffu, e[c], o);
    }
    if ((t & 31) == 0) {
#pragma unroll
        for (int c = 0; c < 6; c++) atomicAdd(&sEff[c], e[c]);
    }
    __syncthreads();

    // node MLP for node r (sEff holds eff_int = 256*eff; scales folded in Wo1t)
    if (t < 45) {
        float a = g_qw.bo1x256[t];
#pragma unroll
        for (int j = 0; j < 16; j++) a += sBn[j] * g_qw.Wo1t[t][j];
#pragma unroll
        for (int c = 0; c < 6; c++) a += sEff[c] * g_qw.Wo1t[t][16 + c];
        sHo1[t] = qrelu_i(a);
    }
    __syncthreads();
    if (t < 22) {
        float a = g_qw.bo2x256[t];
#pragma unroll
        for (int j = 0; j < 45; j++) a += sHo1[j] * g_qw.Wo2t[t][j];
        sHo2[t] = qrelu_i(a);
    }
    __syncthreads();
    if (t < 6) {
        float a = g_qw.bo3x256[t];
#pragma unroll
        for (int j = 0; j < 22; j++) a += sHo2[j] * g_qw.Wo3t[t][j];
        atomicAdd(&g_pooled[b * 8 + t], qrelu_i(a));  // exact integer add
    }
}

// ---------------------------------------------------------------------------
// Kernel C: head (fc1 -> fc2 -> softmax), one block per batch row.
// ---------------------------------------------------------------------------
__global__ void __launch_bounds__(64) head_kernel(float* __restrict__ out)
{
    __shared__ float sp[8];
    __shared__ float sc1[48];
    __shared__ float sl[5];
    const int t = threadIdx.x, b = blockIdx.x;

    if (t < 6) sp[t] = g_pooled[b * 8 + t];
    __syncthreads();
    if (t < 48) {
        float a = g_qw.bc1x256[t];
#pragma unroll
        for (int c = 0; c < 6; c++) a += sp[c] * g_qw.Wc1t[t][c];
        sc1[t] = qrelu_i(a);
    }
    __syncthreads();
    if (t < 5) {
        float a = g_qw.bc2[t];
#pragma unroll
        for (int k = 0; k < 48; k++) a += sc1[k] * g_qw.Wc2t[t][k];
        sl[t] = a;
    }
    __syncthreads();
    if (t == 0) {
        float m = sl[0];
#pragma unroll
        for (int k = 1; k < 5; k++) m = fmaxf(m, sl[k]);
        float ex[5], sum = 0.0f;
#pragma unroll
        for (int k = 0; k < 5; k++) { ex[k] = expf(sl[k] - m); sum += ex[k]; }
        float inv = 1.0f / sum;
#pragma unroll
        for (int k = 0; k < 5; k++) out[b * 5 + k] = ex[k] * inv;
    }
}

// ---------------------------------------------------------------------------
extern "C" void kernel_launch(void* const* d_in, const int* in_sizes, int n_in,
                              void* d_out, int out_size)
{
    (void)in_sizes; (void)n_in; (void)out_size;
    const float* x = (const float*)d_in[0];

    prep_kernel<<<1, 256>>>(
        (const float*)d_in[1],  (const float*)d_in[2],
        (const float*)d_in[3],  (const float*)d_in[4],
        (const float*)d_in[5],  (const float*)d_in[6],
        (const float*)d_in[7],  (const float*)d_in[8],
        (const float*)d_in[9],  (const float*)d_in[10],
        (const float*)d_in[11], (const float*)d_in[12],
        (const float*)d_in[13], (const float*)d_in[14],
        (const float*)d_in[15], (const float*)d_in[16],
        (const float*)d_in[17], (const float*)d_in[18],
        (const float*)d_in[19], (const float*)d_in[20]);

    node_pre_kernel<<<BB, 128>>>(x);

    dim3 grid(NN, BB);
    edge_kernel<<<grid, 128>>>();

    head_kernel<<<BB, 64>>>((float*)d_out);
}

// round 2
// speedup vs baseline: 1.7228x; 1.7228x over previous
#include <cuda_runtime.h>
#include <math.h>

#define BB 128
#define NN 128
#define RT 16                      // receivers per edge-block
#define EDGE_BLOCKS (BB * (NN / RT))   // 128 * 8 = 1024

// ---------------------------------------------------------------------------
// Folded / quantized weights. Activations carried as integer-valued u8
// (value = 256 * true activation); all scales folded at prep time.
// ---------------------------------------------------------------------------
struct QWeights {
    float bnA[16], bnB[16];       // bn = x*bnA + bnB
    float W1x256[32][32];         // [j][k] = 256*qb(fr_w1[j][k]), k<30, else 0
    float b1x256[32];             // 256*qb(fr_b1), pad 0
    unsigned W2p[15][8];          // packed s8: byte u of word j4 = m(fr_w2[4*j4+u][k]), j>=30 -> 0
    int b2i[16];                  // 256*m(fr_b2)   (acc scale = 256*128)
    unsigned W3p[6][4];           // packed s8 over j<15 (pad 16)
    int b3i[8];                   // 256*m(fr_b3)
    float Wo1t[45][24];           // [k][j]: j<16 -> 256*qb(fo_w1[j][k]); j=16..21 -> qb (eff already x256)
    float bo1x256[48];
    float Wo2t[22][48];           // [k][j] = qb(fo_w2[j][k])
    float bo2x256[24];
    float Wo3t[6][24];            // [c][j] = qb(fo_w3[j][c])
    float bo3x256[8];
    float Wc1t[48][8];            // [k][c] = qb(fc_w1[c][k]) (pooled already x256)
    float bc1x256[48];
    float Wc2t[5][48];            // [o][k] = qb(fc_w2[k][o]) / 256
    float bc2[8];
};

__device__ QWeights g_qw;
__device__ __align__(16) float g_bn[BB * NN * 16];
__device__ __align__(16) float g_Ar[BB * NN * 32];
__device__ __align__(16) float g_As[BB * NN * 32];
__device__ float g_pooled[BB * 8];
__device__ unsigned g_ticket;

__device__ __forceinline__ float qb(float x) {
    float y = fminf(fmaxf(x, -1.0f), 127.0f / 128.0f);
    return rintf(y * 128.0f) * (1.0f / 128.0f);
}
__device__ __forceinline__ int qm(float x) {         // integer mantissa of qb (s8 range)
    float y = fminf(fmaxf(x, -1.0f), 127.0f / 128.0f);
    return (int)rintf(y * 128.0f);
}
// 256-scaled qrelu on floats (low-volume paths)
__device__ __forceinline__ float qreluF(float p) {
    return rintf(fminf(fmaxf(p, 0.0f), 255.0f));
}
// round-half-even(N/128) clamped to [0,255] — pure integer, matches jnp.round
__device__ __forceinline__ int rq128(int N) {
    int q = (N + 63 + ((N >> 7) & 1)) >> 7;
    return min(max(q, 0), 255);
}
// clamp to [0,255] and expose integer value in byte 0 (2^23 magic add)
__device__ __forceinline__ unsigned qbyte(float x) {
    return __float_as_uint(fminf(fmaxf(x, 0.0f), 255.0f) + 8388608.0f);
}
__device__ __forceinline__ unsigned pack4b0(unsigned u0, unsigned u1, unsigned u2, unsigned u3) {
    unsigned lo = __byte_perm(u0, u1, 0x0040);
    unsigned hi = __byte_perm(u2, u3, 0x0040);
    return __byte_perm(lo, hi, 0x5410);
}
__device__ __forceinline__ int dp4a_us(unsigned a, unsigned b, int c) {
    int d;
    asm("dp4a.u32.s32 %0, %1, %2, %3;" : "=r"(d) : "r"(a), "r"(b), "r"(c));
    return d;
}

// ---------------------------------------------------------------------------
// Kernel 0: fold/quantize weights, zero accumulators + ticket.
// ---------------------------------------------------------------------------
__global__ void prep_kernel(
    const float* __restrict__ gamma, const float* __restrict__ beta,
    const float* __restrict__ mean,  const float* __restrict__ var,
    const float* __restrict__ fr_w1, const float* __restrict__ fr_b1,
    const float* __restrict__ fr_w2, const float* __restrict__ fr_b2,
    const float* __restrict__ fr_w3, const float* __restrict__ fr_b3,
    const float* __restrict__ fo_w1, const float* __restrict__ fo_b1,
    const float* __restrict__ fo_w2, const float* __restrict__ fo_b2,
    const float* __restrict__ fo_w3, const float* __restrict__ fo_b3,
    const float* __restrict__ fc_w1, const float* __restrict__ fc_b1,
    const float* __restrict__ fc_w2, const float* __restrict__ fc_b2)
{
    const int t = threadIdx.x;
    const int NT = 256;
    unsigned* qwz = reinterpret_cast<unsigned*>(&g_qw);
    const int qn = (int)(sizeof(QWeights) / 4);
    for (int i = t; i < qn; i += NT) qwz[i] = 0u;
    for (int i = t; i < BB * 8; i += NT) g_pooled[i] = 0.0f;
    if (t == 0) g_ticket = 0u;
    __syncthreads();

    if (t < 16) {
        float s = gamma[t] / sqrtf(var[t] + 1e-3f);
        g_qw.bnA[t] = s;
        g_qw.bnB[t] = beta[t] - mean[t] * s;
    }
    for (int i = t; i < 32 * 30; i += NT) { int j = i / 30, k = i % 30; g_qw.W1x256[j][k] = 256.0f * qb(fr_w1[i]); }
    for (int i = t; i < 30; i += NT) g_qw.b1x256[i] = 256.0f * qb(fr_b1[i]);

    for (int i = t; i < 15 * 8; i += NT) {
        int k = i / 8, j4 = i % 8;
        unsigned p = 0;
        for (int u = 0; u < 4; u++) {
            int j = j4 * 4 + u;
            int m = (j < 30) ? qm(fr_w2[j * 15 + k]) : 0;
            p |= ((unsigned)(m & 255)) << (8 * u);
        }
        g_qw.W2p[k][j4] = p;
    }
    for (int i = t; i < 15; i += NT) g_qw.b2i[i] = 256 * qm(fr_b2[i]);

    for (int i = t; i < 6 * 4; i += NT) {
        int c = i / 4, j4 = i % 4;
        unsigned p = 0;
        for (int u = 0; u < 4; u++) {
            int j = j4 * 4 + u;
            int m = (j < 15) ? qm(fr_w3[j * 6 + c]) : 0;
            p |= ((unsigned)(m & 255)) << (8 * u);
        }
        g_qw.W3p[c][j4] = p;
    }
    for (int i = t; i < 6; i += NT) g_qw.b3i[i] = 256 * qm(fr_b3[i]);

    for (int i = t; i < 22 * 45; i += NT) {
        int j = i / 45, k = i % 45;
        float q = qb(fo_w1[i]);
        g_qw.Wo1t[k][j] = (j < 16) ? 256.0f * q : q;
    }
    for (int i = t; i < 45; i += NT) g_qw.bo1x256[i] = 256.0f * qb(fo_b1[i]);
    for (int i = t; i < 45 * 22; i += NT) { int j = i / 22, k = i % 22; g_qw.Wo2t[k][j] = qb(fo_w2[i]); }
    for (int i = t; i < 22; i += NT) g_qw.bo2x256[i] = 256.0f * qb(fo_b2[i]);
    for (int i = t; i < 22 * 6; i += NT) { int j = i / 6, c = i % 6; g_qw.Wo3t[c][j] = qb(fo_w3[i]); }
    for (int i = t; i < 6; i += NT) g_qw.bo3x256[i] = 256.0f * qb(fo_b3[i]);
    for (int i = t; i < 6 * 48; i += NT) { int c = i / 48, k = i % 48; g_qw.Wc1t[k][c] = qb(fc_w1[i]); }
    for (int i = t; i < 48; i += NT) g_qw.bc1x256[i] = 256.0f * qb(fc_b1[i]);
    for (int i = t; i < 48 * 5; i += NT) { int k = i / 5, o = i % 5; g_qw.Wc2t[o][k] = qb(fc_w2[i]) * (1.0f / 256.0f); }
    for (int i = t; i < 5; i += NT) g_qw.bc2[i] = qb(fc_b2[i]);
}

// ---------------------------------------------------------------------------
// Kernel A: per node -> bn, Ar = 256*(bn@W1r)+256*b1, As = 256*(bn@W1s)
// ---------------------------------------------------------------------------
__global__ void __launch_bounds__(128) node_pre_kernel(const float* __restrict__ x)
{
    __shared__ __align__(16) float sW1[32 * 32];
    __shared__ float sb1[32];
    __shared__ float sA[16], sB[16];
    const int t = threadIdx.x, b = blockIdx.x;

    const float* w1g = reinterpret_cast<const float*>(g_qw.W1x256);
    for (int i = t; i < 1024; i += 128) sW1[i] = w1g[i];
    if (t < 32) sb1[t] = g_qw.b1x256[t];
    if (t < 16) { sA[t] = g_qw.bnA[t]; sB[t] = g_qw.bnB[t]; }
    __syncthreads();

    const int n = t;
    const float* xp = x + (size_t)(b * NN + n) * 16;
    float bn[16];
#pragma unroll
    for (int j = 0; j < 16; j++) bn[j] = xp[j] * sA[j] + sB[j];

    float ar[32], as_[32];
#pragma unroll
    for (int k = 0; k < 32; k++) { ar[k] = sb1[k]; as_[k] = 0.0f; }
#pragma unroll
    for (int j = 0; j < 16; j++) {
        float bj = bn[j];
#pragma unroll
        for (int k = 0; k < 32; k++) {
            ar[k]  += bj * sW1[j * 32 + k];
            as_[k] += bj * sW1[(16 + j) * 32 + k];
        }
    }
    float* bno = &g_bn[(size_t)(b * NN + n) * 16];
#pragma unroll
    for (int j = 0; j < 16; j++) bno[j] = bn[j];
    float* aro = &g_Ar[(size_t)(b * NN + n) * 32];
    float* aso = &g_As[(size_t)(b * NN + n) * 32];
#pragma unroll
    for (int k = 0; k < 32; k++) { aro[k] = ar[k]; aso[k] = as_[k]; }
}

// ---------------------------------------------------------------------------
// Kernel B: block (rg, b) handles RT receivers x 128 senders, then the node
// MLP for its RT nodes; last finishing block runs the fc head.
// Everything from h1 on is exact integer arithmetic.
// ---------------------------------------------------------------------------
__global__ void __launch_bounds__(128) edge_kernel(float* __restrict__ out)
{
    __shared__ __align__(16) float sAr[RT][32];
    __shared__ __align__(16) float sBn[RT][16];
    __shared__ __align__(16) unsigned sW2p[15][8];
    __shared__ __align__(16) unsigned sW3p[6][4];
    __shared__ int sb2i[16];
    __shared__ int sb3i[8];
    __shared__ int sEffI[RT][4];     // packed 2x16-bit sums
    __shared__ float sEffF[RT][6];
    __shared__ float sHo1[RT][45];
    __shared__ float sHo2[RT][22];
    __shared__ float sPool[8];
    __shared__ unsigned sLast;

    const int t = threadIdx.x;
    const int rg = blockIdx.x, b = blockIdx.y;
    const int r0 = rg * RT;

    for (int i = t; i < RT * 32; i += 128) (&sAr[0][0])[i] = g_Ar[(size_t)(b * NN + r0) * 32 + i];
    for (int i = t; i < RT * 16; i += 128) (&sBn[0][0])[i] = g_bn[(size_t)(b * NN + r0) * 16 + i];
    {
        const unsigned* w2g = reinterpret_cast<const unsigned*>(g_qw.W2p);
        if (t < 120) (&sW2p[0][0])[t] = w2g[t];
        const unsigned* w3g = reinterpret_cast<const unsigned*>(g_qw.W3p);
        if (t < 24) (&sW3p[0][0])[t] = w3g[t];
        if (t < 15) sb2i[t] = g_qw.b2i[t];
        if (t < 6)  sb3i[t] = g_qw.b3i[t];
        if (t < RT * 4) (&sEffI[0][0])[t] = 0;
        if (t < 8) sPool[t] = 0.0f;
    }
    __syncthreads();

    // sender activations (persist across the receiver loop)
    float as[32];
    {
        const float4* p = reinterpret_cast<const float4*>(&g_As[(size_t)(b * NN + t) * 32]);
#pragma unroll
        for (int i = 0; i < 8; i++) {
            float4 v = p[i];
            as[4 * i + 0] = v.x; as[4 * i + 1] = v.y;
            as[4 * i + 2] = v.z; as[4 * i + 3] = v.w;
        }
    }

#pragma unroll 1
    for (int rr = 0; rr < RT; rr++) {
        const float4* a4 = reinterpret_cast<const float4*>(&sAr[rr][0]);

        // layer 1: h1 = qrelu_i(Ar + As), packed to u8x4 (cols 30,31 are 0 by construction)
        unsigned h1p[8];
#pragma unroll
        for (int j = 0; j < 8; j++) {
            float4 av = a4[j];
            unsigned u0 = qbyte(av.x + as[4 * j + 0]);
            unsigned u1 = qbyte(av.y + as[4 * j + 1]);
            unsigned u2 = qbyte(av.z + as[4 * j + 2]);
            unsigned u3 = qbyte(av.w + as[4 * j + 3]);
            h1p[j] = pack4b0(u0, u1, u2, u3);
        }

        // layer 2: 15 neurons of dp4a over 32 bytes
        int hv[15];
#pragma unroll
        for (int k = 0; k < 15; k++) {
            const uint4* w = reinterpret_cast<const uint4*>(&sW2p[k][0]);
            uint4 wa = w[0], wb = w[1];
            int acc = sb2i[k];
            acc = dp4a_us(h1p[0], wa.x, acc);
            acc = dp4a_us(h1p[1], wa.y, acc);
            acc = dp4a_us(h1p[2], wa.z, acc);
            acc = dp4a_us(h1p[3], wa.w, acc);
            acc = dp4a_us(h1p[4], wb.x, acc);
            acc = dp4a_us(h1p[5], wb.y, acc);
            acc = dp4a_us(h1p[6], wb.z, acc);
            acc = dp4a_us(h1p[7], wb.w, acc);
            hv[k] = rq128(acc);
        }
        unsigned h2p[4];
        h2p[0] = (unsigned)(hv[0]  | (hv[1]  << 8) | (hv[2]  << 16) | (hv[3]  << 24));
        h2p[1] = (unsigned)(hv[4]  | (hv[5]  << 8) | (hv[6]  << 16) | (hv[7]  << 24));
        h2p[2] = (unsigned)(hv[8]  | (hv[9]  << 8) | (hv[10] << 16) | (hv[11] << 24));
        h2p[3] = (unsigned)(hv[12] | (hv[13] << 8) | (hv[14] << 16));

        // layer 3: 6 effect channels
        int ev[6];
#pragma unroll
        for (int c = 0; c < 6; c++) {
            uint4 w = *reinterpret_cast<const uint4*>(&sW3p[c][0]);
            int acc = sb3i[c];
            acc = dp4a_us(h2p[0], w.x, acc);
            acc = dp4a_us(h2p[1], w.y, acc);
            acc = dp4a_us(h2p[2], w.z, acc);
            acc = dp4a_us(h2p[3], w.w, acc);
            ev[c] = rq128(acc);
        }
        const bool diag = (t == r0 + rr);
        int p01 = diag ? 0 : (ev[0] | (ev[1] << 16));
        int p23 = diag ? 0 : (ev[2] | (ev[3] << 16));
        int p45 = diag ? 0 : (ev[4] | (ev[5] << 16));
        p01 = __reduce_add_sync(0xffffffffu, p01);
        p23 = __reduce_add_sync(0xffffffffu, p23);
        p45 = __reduce_add_sync(0xffffffffu, p45);
        if ((t & 31) == 0) {
            atomicAdd(&sEffI[rr][0], p01);
            atomicAdd(&sEffI[rr][1], p23);
            atomicAdd(&sEffI[rr][2], p45);
        }
    }
    __syncthreads();

    // unpack effect sums (each half < 2^15, carry-free)
    if (t < RT * 6) {
        int node = t / 6, c = t % 6;
        int v = sEffI[node][c >> 1];
        int e = (c & 1) ? ((v >> 16) & 0xFFFF) : (v & 0xFFFF);
        sEffF[node][c] = (float)e;
    }
    __syncthreads();

    // fo layer 1: RT*45 = 720 neurons
    for (int idx = t; idx < RT * 45; idx += 128) {
        int node = idx / 45, k = idx % 45;
        float a = g_qw.bo1x256[k];
#pragma unroll
        for (int j = 0; j < 16; j++) a += sBn[node][j] * g_qw.Wo1t[k][j];
#pragma unroll
        for (int c = 0; c < 6; c++) a += sEffF[node][c] * g_qw.Wo1t[k][16 + c];
        sHo1[node][k] = qreluF(a);
    }
    __syncthreads();
    // fo layer 2: RT*22 = 352
    for (int idx = t; idx < RT * 22; idx += 128) {
        int node = idx / 22, k = idx % 22;
        float a = g_qw.bo2x256[k];
#pragma unroll
        for (int j = 0; j < 45; j++) a += sHo1[node][j] * g_qw.Wo2t[k][j];
        sHo2[node][k] = qreluF(a);
    }
    __syncthreads();
    // fo layer 3: RT*6 = 96, accumulate exact-int pooled
    for (int idx = t; idx < RT * 6; idx += 128) {
        int node = idx / 6, c = idx % 6;
        float a = g_qw.bo3x256[c];
#pragma unroll
        for (int j = 0; j < 22; j++) a += sHo2[node][j] * g_qw.Wo3t[c][j];
        atomicAdd(&sPool[c], qreluF(a));
    }
    __syncthreads();
    if (t < 6) atomicAdd(&g_pooled[b * 8 + t], sPool[t]);

    // last-block ticket -> run the head inline
    if (t == 0) {
        __threadfence();
        unsigned done = atomicAdd(&g_ticket, 1u);
        sLast = (done == EDGE_BLOCKS - 1) ? 1u : 0u;
    }
    __syncthreads();
    if (sLast) {
        __threadfence();
        const int bb = t;  // 128 threads, one batch row each
        float pl[6];
#pragma unroll
        for (int c = 0; c < 6; c++) pl[c] = g_pooled[bb * 8 + c];
        float lg[5];
#pragma unroll
        for (int o = 0; o < 5; o++) lg[o] = g_qw.bc2[o];
#pragma unroll 4
        for (int k = 0; k < 48; k++) {
            float a = g_qw.bc1x256[k];
#pragma unroll
            for (int c = 0; c < 6; c++) a += pl[c] * g_qw.Wc1t[k][c];
            float c1 = qreluF(a);
#pragma unroll
            for (int o = 0; o < 5; o++) lg[o] += c1 * g_qw.Wc2t[o][k];
        }
        float m = lg[0];
#pragma unroll
        for (int o = 1; o < 5; o++) m = fmaxf(m, lg[o]);
        float ex[5], sum = 0.0f;
#pragma unroll
        for (int o = 0; o < 5; o++) { ex[o] = expf(lg[o] - m); sum += ex[o]; }
        float inv = 1.0f / sum;
#pragma unroll
        for (int o = 0; o < 5; o++) out[bb * 5 + o] = ex[o] * inv;
    }
}

// ---------------------------------------------------------------------------
extern "C" void kernel_launch(void* const* d_in, const int* in_sizes, int n_in,
                              void* d_out, int out_size)
{
    (void)in_sizes; (void)n_in; (void)out_size;
    const float* x = (const float*)d_in[0];

    prep_kernel<<<1, 256>>>(
        (const float*)d_in[1],  (const float*)d_in[2],
        (const float*)d_in[3],  (const float*)d_in[4],
        (const float*)d_in[5],  (const float*)d_in[6],
        (const float*)d_in[7],  (const float*)d_in[8],
        (const float*)d_in[9],  (const float*)d_in[10],
        (const float*)d_in[11], (const float*)d_in[12],
        (const float*)d_in[13], (const float*)d_in[14],
        (const float*)d_in[15], (const float*)d_in[16],
        (const float*)d_in[17], (const float*)d_in[18],
        (const float*)d_in[19], (const float*)d_in[20]);

    node_pre_kernel<<<BB, 128>>>(x);

    dim3 grid(NN / RT, BB);
    edge_kernel<<<grid, 128>>>((float*)d_out);
}

// round 3
// speedup vs baseline: 3.0000x; 1.7414x over previous
#include <cuda_runtime.h>
#include <math.h>

#define BB 128
#define NN 128
#define RT 16
#define EDGE_BLOCKS (BB * (NN / RT))   // 1024

// ---------------------------------------------------------------------------
// Folded / quantized weights (activations carried as 256-scaled integers).
// ---------------------------------------------------------------------------
struct QWeights {
    // edge-MLP weights (first 42 uint4, copied to smem as one chunk)
    unsigned W2p[15][8];          // packed s8 [neuron][j/4]
    int b2i[16];                  // 256*m(fr_b2), pad 0
    unsigned W3p[6][4];
    int b3i[8];
    // fo weights, input-major (598 uint4 chunk)
    float Wo1s[22][48];           // [j][k]: j<16 scaled x256, j=16..21 x1; k>=45 pad 0
    float bo1[48];
    float Wo2s[45][24];           // [j][k], k>=22 pad 0
    float bo2[24];
    float Wo3s[22][8];            // [j][c], c>=6 pad 0
    float bo3[8];
    // head
    float Wc1t[48][8];            // [k][c]
    float bc1[48];
    float Wc2t[5][48];            // [o][k] = qb/256
    float bc2[8];
};

__device__ QWeights g_qw;
__device__ __align__(16) float g_bn[BB * NN * 16];
__device__ __align__(16) float g_Ar[BB * NN * 32];
__device__ __align__(16) float g_As[BB * NN * 32];
__device__ float g_part[BB][NN / RT][6];
__device__ unsigned g_ticket;   // zero-init; self-resets each launch

__device__ __forceinline__ float qb(float x) {
    float y = fminf(fmaxf(x, -1.0f), 127.0f / 128.0f);
    return rintf(y * 128.0f) * (1.0f / 128.0f);
}
__device__ __forceinline__ int qm(float x) {
    float y = fminf(fmaxf(x, -1.0f), 127.0f / 128.0f);
    return (int)rintf(y * 128.0f);
}
__device__ __forceinline__ float qreluF(float p) {
    return rintf(fminf(fmaxf(p, 0.0f), 255.0f));
}
// round-half-even + clamp [0,255] + zero-extend, on the conversion pipe
__device__ __forceinline__ unsigned cvt_u8(float x) {
    unsigned short h;
    asm("cvt.rni.sat.u8.f32 %0, %1;" : "=h"(h) : "f"(x));
    return (unsigned)h;
}
__device__ __forceinline__ unsigned requant(int acc) {
    return cvt_u8((float)acc * (1.0f / 128.0f));   // exact: |acc| < 2^23
}
__device__ __forceinline__ unsigned pk4(unsigned a, unsigned b, unsigned c, unsigned d) {
    return __byte_perm(__byte_perm(a, b, 0x0040), __byte_perm(c, d, 0x0040), 0x5410);
}
__device__ __forceinline__ int dp4a_us(unsigned a, unsigned b, int c) {
    int d;
    asm("dp4a.u32.s32 %0, %1, %2, %3;" : "=r"(d) : "r"(a), "r"(b), "r"(c));
    return d;
}

// ---------------------------------------------------------------------------
// prep: 4 parallel blocks, disjoint sections, explicit pad writes.
// ---------------------------------------------------------------------------
__global__ void __launch_bounds__(128) prep_kernel(
    const float* __restrict__ fr_w2, const float* __restrict__ fr_b2,
    const float* __restrict__ fr_w3, const float* __restrict__ fr_b3,
    const float* __restrict__ fo_w1, const float* __restrict__ fo_b1,
    const float* __restrict__ fo_w2, const float* __restrict__ fo_b2,
    const float* __restrict__ fo_w3, const float* __restrict__ fo_b3,
    const float* __restrict__ fc_w1, const float* __restrict__ fc_b1,
    const float* __restrict__ fc_w2, const float* __restrict__ fc_b2)
{
    const int t = threadIdx.x;
    const int blk = blockIdx.x;
    if (blk == 0) {
        for (int i = t; i < 15 * 8; i += 128) {
            int k = i / 8, j4 = i % 8;
            unsigned p = 0;
            for (int u = 0; u < 4; u++) {
                int j = j4 * 4 + u;
                int m = (j < 30) ? qm(fr_w2[j * 15 + k]) : 0;
                p |= ((unsigned)(m & 255)) << (8 * u);
            }
            g_qw.W2p[k][j4] = p;
        }
        if (t < 16) g_qw.b2i[t] = (t < 15) ? 256 * qm(fr_b2[t]) : 0;
        for (int i = t; i < 6 * 4; i += 128) {
            int c = i / 4, j4 = i % 4;
            unsigned p = 0;
            for (int u = 0; u < 4; u++) {
                int j = j4 * 4 + u;
                int m = (j < 15) ? qm(fr_w3[j * 6 + c]) : 0;
                p |= ((unsigned)(m & 255)) << (8 * u);
            }
            g_qw.W3p[c][j4] = p;
        }
        if (t < 8) g_qw.b3i[t] = (t < 6) ? 256 * qm(fr_b3[t]) : 0;
    } else if (blk == 1) {
        for (int i = t; i < 22 * 48; i += 128) {
            int j = i / 48, k = i % 48;
            float v = (k < 45) ? qb(fo_w1[j * 45 + k]) : 0.0f;
            g_qw.Wo1s[j][k] = (j < 16) ? 256.0f * v : v;
        }
        if (t < 48) g_qw.bo1[t] = (t < 45) ? 256.0f * qb(fo_b1[t]) : 0.0f;
    } else if (blk == 2) {
        for (int i = t; i < 45 * 24; i += 128) {
            int j = i / 24, k = i % 24;
            g_qw.Wo2s[j][k] = (k < 22) ? qb(fo_w2[j * 22 + k]) : 0.0f;
        }
        if (t < 24) g_qw.bo2[t] = (t < 22) ? 256.0f * qb(fo_b2[t]) : 0.0f;
    } else {
        for (int i = t; i < 22 * 8; i += 128) {
            int j = i / 8, c = i % 8;
            g_qw.Wo3s[j][c] = (c < 6) ? qb(fo_w3[j * 6 + c]) : 0.0f;
        }
        if (t < 8) g_qw.bo3[t] = (t < 6) ? 256.0f * qb(fo_b3[t]) : 0.0f;
        for (int i = t; i < 48 * 8; i += 128) {
            int k = i / 8, c = i % 8;
            g_qw.Wc1t[k][c] = (c < 6) ? qb(fc_w1[c * 48 + k]) : 0.0f;
        }
        if (t < 48) g_qw.bc1[t] = 256.0f * qb(fc_b1[t]);
        for (int i = t; i < 5 * 48; i += 128) {
            int o = i / 48, k = i % 48;
            g_qw.Wc2t[o][k] = qb(fc_w2[k * 5 + o]) * (1.0f / 256.0f);
        }
        if (t < 8) g_qw.bc2[t] = (t < 5) ? qb(fc_w2 ? fc_b2[t] : 0.0f) : 0.0f;
    }
}

// ---------------------------------------------------------------------------
// node_pre: self-sufficient (quantizes W1/bn itself). bn, Ar, As per node.
// ---------------------------------------------------------------------------
__global__ void __launch_bounds__(128) node_pre_kernel(
    const float* __restrict__ x,
    const float* __restrict__ gamma, const float* __restrict__ beta,
    const float* __restrict__ mean,  const float* __restrict__ var,
    const float* __restrict__ fr_w1, const float* __restrict__ fr_b1)
{
    __shared__ __align__(16) float sW1[32 * 32];
    __shared__ float sb1[32];
    __shared__ float sA[16], sB[16];
    const int t = threadIdx.x, b = blockIdx.x;

    for (int i = t; i < 1024; i += 128) {
        int j = i >> 5, k = i & 31;
        sW1[i] = (k < 30) ? 256.0f * qb(fr_w1[j * 30 + k]) : 0.0f;
    }
    if (t < 32) sb1[t] = (t < 30) ? 256.0f * qb(fr_b1[t]) : 0.0f;
    if (t < 16) {
        float s = gamma[t] / sqrtf(var[t] + 1e-3f);
        sA[t] = s;
        sB[t] = beta[t] - mean[t] * s;
    }
    __syncthreads();

    const int n = t;
    const float* xp = x + (size_t)(b * NN + n) * 16;
    float bn[16];
#pragma unroll
    for (int j = 0; j < 16; j++) bn[j] = xp[j] * sA[j] + sB[j];

    float ar[32], as_[32];
#pragma unroll
    for (int k = 0; k < 32; k++) { ar[k] = sb1[k]; as_[k] = 0.0f; }
#pragma unroll
    for (int j = 0; j < 16; j++) {
        float bj = bn[j];
#pragma unroll
        for (int k = 0; k < 32; k++) {
            ar[k]  += bj * sW1[j * 32 + k];
            as_[k] += bj * sW1[(16 + j) * 32 + k];
        }
    }
    float* bno = &g_bn[(size_t)(b * NN + n) * 16];
#pragma unroll
    for (int j = 0; j < 16; j++) bno[j] = bn[j];
    float* aro = &g_Ar[(size_t)(b * NN + n) * 32];
    float* aso = &g_As[(size_t)(b * NN + n) * 32];
#pragma unroll
    for (int k = 0; k < 32; k++) { aro[k] = ar[k]; aso[k] = as_[k]; }
}

// ---------------------------------------------------------------------------
// edge kernel: (rg, b) -> RT receivers x 128 senders + node MLP; last block
// runs the fc head inline. Integer-exact throughout.
// ---------------------------------------------------------------------------
struct EdgeW { unsigned W2p[15][8]; int b2i[16]; unsigned W3p[6][4]; int b3i[8]; };
struct FoW {
    float Wo1s[22][48]; float bo1[48];
    float Wo2s[45][24]; float bo2[24];
    float Wo3s[22][8];  float bo3[8];
};

__global__ void __launch_bounds__(128) edge_kernel(float* __restrict__ out)
{
    __shared__ __align__(16) EdgeW sEw;
    __shared__ __align__(16) FoW sFo;
    __shared__ __align__(16) float sAr[RT][32];
    __shared__ __align__(16) float sBn[RT][16];
    __shared__ int sEffI[RT][4];
    __shared__ float sEffF[RT][6];
    __shared__ float sHo1[RT][45];
    __shared__ float sHo2[RT][22];
    __shared__ float sPool[8];
    __shared__ unsigned sLast;

    const int t = threadIdx.x;
    const int rg = blockIdx.x, b = blockIdx.y;
    const int r0 = rg * RT;

    {
        const uint4* es = reinterpret_cast<const uint4*>(&g_qw);
        uint4* ed = reinterpret_cast<uint4*>(&sEw);
        if (t < 42) ed[t] = es[t];
        const uint4* fs = reinterpret_cast<const uint4*>(&g_qw.Wo1s[0][0]);
        uint4* fd = reinterpret_cast<uint4*>(&sFo);
        for (int i = t; i < 598; i += 128) fd[i] = fs[i];
        const uint4* ars = reinterpret_cast<const uint4*>(&g_Ar[(size_t)(b * NN + r0) * 32]);
        uint4* ard = reinterpret_cast<uint4*>(&sAr[0][0]);
        if (t < 128) ard[t] = ars[t];
        const uint4* bns = reinterpret_cast<const uint4*>(&g_bn[(size_t)(b * NN + r0) * 16]);
        uint4* bnd = reinterpret_cast<uint4*>(&sBn[0][0]);
        if (t < 64) bnd[t] = bns[t];
        if (t < RT * 4) (&sEffI[0][0])[t] = 0;
        if (t < 8) sPool[t] = 0.0f;
    }

    // sender activations in registers
    float as[32];
    {
        const float4* p = reinterpret_cast<const float4*>(&g_As[(size_t)(b * NN + t) * 32]);
#pragma unroll
        for (int i = 0; i < 8; i++) {
            float4 v = p[i];
            as[4 * i + 0] = v.x; as[4 * i + 1] = v.y;
            as[4 * i + 2] = v.z; as[4 * i + 3] = v.w;
        }
    }
    __syncthreads();

#pragma unroll 1
    for (int rr = 0; rr < RT; rr++) {
        const float4* a4 = reinterpret_cast<const float4*>(&sAr[rr][0]);

        // layer 1: one FADD + one cvt.sat per element, PRMT pack
        unsigned h1p[8];
#pragma unroll
        for (int j = 0; j < 8; j++) {
            float4 av = a4[j];
            unsigned u0 = cvt_u8(av.x + as[4 * j + 0]);
            unsigned u1 = cvt_u8(av.y + as[4 * j + 1]);
            unsigned u2 = cvt_u8(av.z + as[4 * j + 2]);
            unsigned u3 = cvt_u8(av.w + as[4 * j + 3]);
            h1p[j] = pk4(u0, u1, u2, u3);
        }

        // layer 2: 15 x 8 dp4a, conversion-pipe requant
        unsigned q[15];
#pragma unroll
        for (int k = 0; k < 15; k++) {
            const uint4* w = reinterpret_cast<const uint4*>(&sEw.W2p[k][0]);
            uint4 wa = w[0], wb = w[1];
            int acc = sEw.b2i[k];
            acc = dp4a_us(h1p[0], wa.x, acc);
            acc = dp4a_us(h1p[1], wa.y, acc);
            acc = dp4a_us(h1p[2], wa.z, acc);
            acc = dp4a_us(h1p[3], wa.w, acc);
            acc = dp4a_us(h1p[4], wb.x, acc);
            acc = dp4a_us(h1p[5], wb.y, acc);
            acc = dp4a_us(h1p[6], wb.z, acc);
            acc = dp4a_us(h1p[7], wb.w, acc);
            q[k] = requant(acc);
        }
        unsigned h2p0 = pk4(q[0], q[1], q[2], q[3]);
        unsigned h2p1 = pk4(q[4], q[5], q[6], q[7]);
        unsigned h2p2 = pk4(q[8], q[9], q[10], q[11]);
        unsigned h2p3 = __byte_perm(__byte_perm(q[12], q[13], 0x0040), q[14], 0x7410);

        // layer 3: 6 channels
        unsigned e[6];
#pragma unroll
        for (int c = 0; c < 6; c++) {
            uint4 w = *reinterpret_cast<const uint4*>(&sEw.W3p[c][0]);
            int acc = sEw.b3i[c];
            acc = dp4a_us(h2p0, w.x, acc);
            acc = dp4a_us(h2p1, w.y, acc);
            acc = dp4a_us(h2p2, w.z, acc);
            acc = dp4a_us(h2p3, w.w, acc);
            e[c] = requant(acc);
        }
        const bool diag = (t == r0 + rr);
        int p01 = diag ? 0 : (int)__byte_perm(e[0], e[1], 0x7430);
        int p23 = diag ? 0 : (int)__byte_perm(e[2], e[3], 0x7430);
        int p45 = diag ? 0 : (int)__byte_perm(e[4], e[5], 0x7430);
        p01 = __reduce_add_sync(0xffffffffu, p01);
        p23 = __reduce_add_sync(0xffffffffu, p23);
        p45 = __reduce_add_sync(0xffffffffu, p45);
        if ((t & 31) == 0) {
            atomicAdd(&sEffI[rr][0], p01);
            atomicAdd(&sEffI[rr][1], p23);
            atomicAdd(&sEffI[rr][2], p45);
        }
    }
    __syncthreads();

    // unpack 16-bit halves (sums <= 127*255 < 2^15, carry-free)
    if (t < RT * 6) {
        int node = t / 6, c = t % 6;
        int v = sEffI[node][c >> 1];
        sEffF[node][c] = (float)((c & 1) ? ((v >> 16) & 0xFFFF) : (v & 0xFFFF));
    }
    __syncthreads();

    // fo layer 1 (720 neurons)
    for (int idx = t; idx < RT * 45; idx += 128) {
        int node = idx / 45, k = idx % 45;
        float a = sFo.bo1[k];
#pragma unroll
        for (int j = 0; j < 16; j++) a += sBn[node][j] * sFo.Wo1s[j][k];
#pragma unroll
        for (int c = 0; c < 6; c++) a += sEffF[node][c] * sFo.Wo1s[16 + c][k];
        sHo1[node][k] = qreluF(a);
    }
    __syncthreads();
    // fo layer 2 (352)
    for (int idx = t; idx < RT * 22; idx += 128) {
        int node = idx / 22, k = idx % 22;
        float a = sFo.bo2[k];
#pragma unroll
        for (int j = 0; j < 45; j++) a += sHo1[node][j] * sFo.Wo2s[j][k];
        sHo2[node][k] = qreluF(a);
    }
    __syncthreads();
    // fo layer 3 (96) -> block pool
    for (int idx = t; idx < RT * 6; idx += 128) {
        int node = idx / 6, c = idx % 6;
        float a = sFo.bo3[c];
#pragma unroll
        for (int j = 0; j < 22; j++) a += sHo2[node][j] * sFo.Wo3s[j][c];
        atomicAdd(&sPool[c], qreluF(a));
    }
    __syncthreads();
    if (t < 6) g_part[b][rg][t] = sPool[t];

    // last-block ticket -> fc head inline
    if (t == 0) {
        __threadfence();
        unsigned done = atomicAdd(&g_ticket, 1u);
        sLast = (done == EDGE_BLOCKS - 1) ? 1u : 0u;
    }
    __syncthreads();
    if (sLast) {
        __threadfence();
        if (t == 0) g_ticket = 0;   // self-reset for graph replay
        const int bb = t;
        float pl[6];
#pragma unroll
        for (int c = 0; c < 6; c++) {
            float s = 0.0f;
#pragma unroll
            for (int g = 0; g < NN / RT; g++) s += g_part[bb][g][c];
            pl[c] = s;
        }
        float lg[5];
#pragma unroll
        for (int o = 0; o < 5; o++) lg[o] = g_qw.bc2[o];
#pragma unroll 4
        for (int k = 0; k < 48; k++) {
            float a = g_qw.bc1[k];
#pragma unroll
            for (int c = 0; c < 6; c++) a += pl[c] * g_qw.Wc1t[k][c];
            float c1 = qreluF(a);
#pragma unroll
            for (int o = 0; o < 5; o++) lg[o] += c1 * g_qw.Wc2t[o][k];
        }
        float m = lg[0];
#pragma unroll
        for (int o = 1; o < 5; o++) m = fmaxf(m, lg[o]);
        float ex[5], sum = 0.0f;
#pragma unroll
        for (int o = 0; o < 5; o++) { ex[o] = expf(lg[o] - m); sum += ex[o]; }
        float inv = 1.0f / sum;
#pragma unroll
        for (int o = 0; o < 5; o++) out[bb * 5 + o] = ex[o] * inv;
    }
}

// ---------------------------------------------------------------------------
extern "C" void kernel_launch(void* const* d_in, const int* in_sizes, int n_in,
                              void* d_out, int out_size)
{
    (void)in_sizes; (void)n_in; (void)out_size;

    node_pre_kernel<<<BB, 128>>>(
        (const float*)d_in[0],
        (const float*)d_in[1], (const float*)d_in[2],
        (const float*)d_in[3], (const float*)d_in[4],
        (const float*)d_in[5], (const float*)d_in[6]);

    prep_kernel<<<4, 128>>>(
        (const float*)d_in[7],  (const float*)d_in[8],
        (const float*)d_in[9],  (const float*)d_in[10],
        (const float*)d_in[11], (const float*)d_in[12],
        (const float*)d_in[13], (const float*)d_in[14],
        (const float*)d_in[15], (const float*)d_in[16],
        (const float*)d_in[17], (const float*)d_in[18],
        (const float*)d_in[19], (const float*)d_in[20]);

    dim3 grid(NN / RT, BB);
    edge_kernel<<<grid, 128>>>((float*)d_out);
}